// round 12
// baseline (speedup 1.0000x reference)
#include <cuda_runtime.h>

#define NF    32
#define NDOF  29
#define BLK   64            // 64 batches per block, 1 thread per batch, 2 warps
#define CH    2             // frames per chunk
#define TS    28            // slab floats per batch: 2 frames * 12 + 4 pad

struct FKConst {
    float4 cst[NF * 9];     // per (frame, row j 0..2): cA, cB, cC
    int    slot[NF];
    int    mslot[NF];
    float  mm[NF];
    float  mo[NF];
};

__constant__ FKConst c_fk;
__device__   FKConst g_fk;

// ---------------------------------------------------------------------------
// Prep kernel: derive per-(frame,row) constants + ctrl/mimic meta (uniform).
//   cA = (O_j.xyz, O_j.w)
//   cB = (O_j x k [revolute], O_j.k [prismatic])
//   cC = ((O_j.k)k - O_j.xyz [revolute], 0)
// L_j.xyz = cA + sn*cB + (1-cs)*cC ;  L_j.w = a*cB.w + cA.w
// ---------------------------------------------------------------------------
__global__ void fk_prep(const float* __restrict__ axes,
                        const float* __restrict__ origins,
                        const float* __restrict__ mmult,
                        const float* __restrict__ moff,
                        const int*   __restrict__ ctrl,
                        const int*   __restrict__ msrc,
                        const int*   __restrict__ mdst,
                        const int*   __restrict__ types)
{
    const int tid = threadIdx.x;     // 128 threads
    if (tid < NF * 3) {
        const int f  = tid / 3;
        const int rr = tid - f * 3;
        const float4 orow = *reinterpret_cast<const float4*>(origins + f * 16 + rr * 4);
        const float kx = axes[f * 3 + 0], ky = axes[f * 3 + 1], kz = axes[f * 3 + 2];
        const int   ty = types[f];
        const float vr = orow.x * kx + orow.y * ky + orow.z * kz;
        float bx = 0.f, by = 0.f, bz = 0.f, cx = 0.f, cy = 0.f, cz = 0.f, ve = 0.f;
        if (ty == 1) {
            bx = orow.y * kz - orow.z * ky;
            by = orow.z * kx - orow.x * kz;
            bz = orow.x * ky - orow.y * kx;
            cx = fmaf(vr, kx, -orow.x);
            cy = fmaf(vr, ky, -orow.y);
            cz = fmaf(vr, kz, -orow.z);
        } else if (ty == 2) {
            ve = vr;
        }
        g_fk.cst[(f * 3 + rr) * 3 + 0] = make_float4(orow.x, orow.y, orow.z, orow.w);
        g_fk.cst[(f * 3 + rr) * 3 + 1] = make_float4(bx, by, bz, ve);
        g_fk.cst[(f * 3 + rr) * 3 + 2] = make_float4(cx, cy, cz, 0.f);
    }
    if (tid < NF) {
        const int f = tid;
        int slot = -1;
        for (int j = 0; j < NDOF; ++j) if (ctrl[j] == f) slot = j;
        g_fk.slot[f] = slot;
        int ms = -1; float mm = 0.f, mo = 0.f;
        for (int m = 0; m < 2; ++m) {
            if (mdst[m] == f) {
                const int sf = msrc[m];
                for (int j = 0; j < NDOF; ++j) if (ctrl[j] == sf) ms = j;
                mm = mmult[m]; mo = moff[m];
            }
        }
        g_fk.mslot[f] = ms; g_fk.mm[f] = mm; g_fk.mo[f] = mo;
    }
}

__global__ void __launch_bounds__(BLK, 7)
fk_kernel(const float* __restrict__ ja,        // [B, 29]
          float*       __restrict__ out,       // [B, 32, 4, 4]
          int Bn)
{
    __shared__ __align__(16) float s_slab[BLK * TS];   // 7 KB (warp-private halves)
    __shared__ float s_angF[NF * BLK];                 // 8 KB

    const int tid  = threadIdx.x;
    const int lane = tid & 31;
    const int wid  = tid >> 5;
    const int b0   = blockIdx.x * BLK;

    // ---- stage raw joint angles into s_angF region (aliased), coalesced ----
    float* s_raw = s_angF;                  // 64*29 = 1856 <= 2048 ✓
    for (int i = tid; i < BLK * NDOF; i += BLK) {
        const int bb = i / NDOF;
        s_raw[i] = (b0 + bb < Bn) ? ja[(size_t)b0 * NDOF + i] : 0.f;
    }
    __syncthreads();

    // ---- resolve final per-(frame,batch) angles (meta from constant bank) ----
    {
        float av[NF];
        const float* raw = s_raw + tid * NDOF;
        #pragma unroll
        for (int f = 0; f < NF; ++f) {
            const int sl = c_fk.slot[f];
            float a;
            if (sl >= 0) a = raw[sl];
            else {
                const int ms = c_fk.mslot[f];
                a = (ms >= 0) ? fmaf(raw[ms], c_fk.mm[f], c_fk.mo[f]) : 0.f;
            }
            av[f] = a;
        }
        __syncthreads();
        #pragma unroll
        for (int f = 0; f < NF; ++f) s_angF[f * BLK + tid] = av[f];
    }
    __syncthreads();

    // ---- main chain: 2-frame phase-split chunks, warp-autonomous flush ----
    float P[12];
    #pragma unroll
    for (int j = 0; j < 12; ++j) P[j] = 0.f;
    P[0] = 1.f; P[5] = 1.f; P[10] = 1.f;
    float Q[12];
    #pragma unroll
    for (int j = 0; j < 12; ++j) Q[j] = 0.f;

    float* const wslab = s_slab + wid * (32 * TS);
    float4* const out4 = reinterpret_cast<float4*>(out);

    #pragma unroll
    for (int c = 0; c < NF / CH; ++c) {
        // -- phase A: build CH independent local transforms (constant-bank operands) --
        float L[CH][12];
        #pragma unroll
        for (int ff = 0; ff < CH; ++ff) {
            const int f = c * CH + ff;
            const float a = s_angF[f * BLK + tid];
            const float sn = __sinf(a);
            const float cs = __cosf(a);
            const float C = 1.f - cs;
            #pragma unroll
            for (int j = 0; j < 3; ++j) {
                const float4 cA = c_fk.cst[(f * 3 + j) * 3 + 0];
                const float4 cB = c_fk.cst[(f * 3 + j) * 3 + 1];
                const float4 cC = c_fk.cst[(f * 3 + j) * 3 + 2];
                L[ff][j * 4 + 0] = fmaf(C, cC.x, fmaf(sn, cB.x, cA.x));
                L[ff][j * 4 + 1] = fmaf(C, cC.y, fmaf(sn, cB.y, cA.y));
                L[ff][j * 4 + 2] = fmaf(C, cC.z, fmaf(sn, cB.z, cA.z));
                L[ff][j * 4 + 3] = fmaf(a, cB.w, cA.w);
            }
        }

        // -- phase B: serial chain updates + stage --
        #pragma unroll
        for (int ff = 0; ff < CH; ++ff) {
            const int f = c * CH + ff;
            if (f >= 30) {
                #pragma unroll
                for (int j = 0; j < 12; ++j) P[j] = Q[j];
            }
            #pragma unroll
            for (int rr = 0; rr < 3; ++rr) {
                const float p0 = P[rr * 4 + 0], p1 = P[rr * 4 + 1];
                const float p2 = P[rr * 4 + 2], p3 = P[rr * 4 + 3];
                P[rr * 4 + 0] = fmaf(p0, L[ff][0], fmaf(p1, L[ff][4], p2 * L[ff][8]));
                P[rr * 4 + 1] = fmaf(p0, L[ff][1], fmaf(p1, L[ff][5], p2 * L[ff][9]));
                P[rr * 4 + 2] = fmaf(p0, L[ff][2], fmaf(p1, L[ff][6], p2 * L[ff][10]));
                P[rr * 4 + 3] = fmaf(p0, L[ff][3], fmaf(p1, L[ff][7], fmaf(p2, L[ff][11], p3)));
            }
            if (f == 10) {
                #pragma unroll
                for (int j = 0; j < 12; ++j) Q[j] = P[j];
            }
            float4* sp = reinterpret_cast<float4*>(wslab + lane * TS + ff * 12);
            sp[0] = make_float4(P[0], P[1], P[2],  P[3]);
            sp[1] = make_float4(P[4], P[5], P[6],  P[7]);
            sp[2] = make_float4(P[8], P[9], P[10], P[11]);
        }

        __syncwarp();

        // -- flush: each iter = 4 batches x 128 B contiguous (fully coalesced) --
        #pragma unroll
        for (int it = 0; it < 8; ++it) {
            const int v = it * 32 + lane;
            const int b = v >> 3;               // warp-local batch (0..31)
            const int w = v & 7;                // frame*4 + row within chunk
            const int fi = w >> 2;
            const int rr = w & 3;
            float4 val;
            if (rr < 3) val = *reinterpret_cast<const float4*>(wslab + b * TS + fi * 12 + rr * 4);
            else        val = make_float4(0.f, 0.f, 0.f, 1.f);
            const int gbat = b0 + (wid << 5) + b;
            if (gbat < Bn)
                out4[(size_t)gbat * (NF * 4) + c * (CH * 4) + w] = val;
        }

        __syncwarp();
    }
}

extern "C" void kernel_launch(void* const* d_in, const int* in_sizes, int n_in,
                              void* d_out, int out_size) {
    const float* ja      = (const float*)d_in[0];
    const float* axes    = (const float*)d_in[1];
    const float* origins = (const float*)d_in[2];
    const float* mm      = (const float*)d_in[3];
    const float* mo      = (const float*)d_in[4];
    const int*   ctrl    = (const int*)d_in[5];
    const int*   msrc    = (const int*)d_in[6];
    const int*   mdst    = (const int*)d_in[7];
    const int*   types   = (const int*)d_in[8];
    float*       out     = (float*)d_out;

    const int Bn = in_sizes[0] / NDOF;

    // 1) derive constants on device
    fk_prep<<<1, 128>>>(axes, origins, mm, mo, ctrl, msrc, mdst, types);

    // 2) copy into constant bank (D2D async memcpy — graph-capturable)
    void* g_ptr = nullptr;
    cudaGetSymbolAddress(&g_ptr, g_fk);
    cudaMemcpyToSymbolAsync(c_fk, g_ptr, sizeof(FKConst), 0, cudaMemcpyDeviceToDevice);

    // 3) main kernel
    const int grid = (Bn + BLK - 1) / BLK;
    fk_kernel<<<grid, BLK>>>(ja, out, Bn);
}